// round 1
// baseline (speedup 1.0000x reference)
#include <cuda_runtime.h>

#define Nn 65536
#define Kk 16
#define NK (Nn*Kk)

typedef unsigned long long ull;

__device__ __forceinline__ ull pk2(float lo, float hi){
    ull r; asm("mov.b64 %0, {%1,%2};" : "=l"(r) : "f"(lo), "f"(hi)); return r;
}
__device__ __forceinline__ float2 upk2(ull v){
    float2 r; asm("mov.b64 {%0,%1}, %2;" : "=f"(r.x), "=f"(r.y) : "l"(v)); return r;
}
__device__ __forceinline__ void ffma2(ull &acc, ull a, ull b){
    asm("fma.rn.f32x2 %0, %1, %2, %0;" : "+l"(acc) : "l"(a), "l"(b));
}

// ---------------- scratch (device globals; no allocation) ----------------
__device__ float g_M1[10];      // sum of concat features
__device__ float g_M2[55];      // upper-triangle second moments
__device__ float g_w1p[1280];   // folded w1' = w1 * a1   (10 x 128)
__device__ float g_c1[128];     // folded const = be1 - m*a1
__device__ float g_sum2[64];
__device__ float g_sumsq2[64];
__device__ float g_a2[64];
__device__ float g_c2[64];

// ---------------- K0: zero accumulators (graph-replay safe) --------------
__global__ void k_zero(){
    int t = threadIdx.x;
    if (t < 10) g_M1[t] = 0.f;
    if (t < 55) g_M2[t] = 0.f;
    if (t < 64){ g_sum2[t] = 0.f; g_sumsq2[t] = 0.f; }
}

// ---------------- K1: moments of concat over all (n,k) -------------------
__global__ void k_stats(const float* __restrict__ p){
    float m1[10], m2[55];
#pragma unroll
    for (int i=0;i<10;i++) m1[i]=0.f;
#pragma unroll
    for (int i=0;i<55;i++) m2[i]=0.f;
    int tid = blockIdx.x*blockDim.x + threadIdx.x;
    int nth = gridDim.x*blockDim.x;
    for (int r = tid; r < NK; r += nth){
        int n = r >> 4, k = r & 15;
        const float* pc = p + n*48;
        float c[10];
        c[0]=pc[0];     c[1]=pc[1];     c[2]=pc[2];
        c[3]=pc[3*k];   c[4]=pc[3*k+1]; c[5]=pc[3*k+2];
        c[6]=c[0]-c[3]; c[7]=c[1]-c[4]; c[8]=c[2]-c[5];
        c[9]=sqrtf(c[6]*c[6]+c[7]*c[7]+c[8]*c[8]);
        int t = 0;
#pragma unroll
        for (int a=0;a<10;a++){
            m1[a] += c[a];
#pragma unroll
            for (int b=a;b<10;b++) m2[t++] += c[a]*c[b];
        }
    }
#pragma unroll
    for (int off=16; off>0; off>>=1){
#pragma unroll
        for (int i=0;i<10;i++) m1[i] += __shfl_down_sync(0xffffffffu, m1[i], off);
#pragma unroll
        for (int i=0;i<55;i++) m2[i] += __shfl_down_sync(0xffffffffu, m2[i], off);
    }
    if ((threadIdx.x & 31) == 0){
#pragma unroll
        for (int i=0;i<10;i++) atomicAdd(&g_M1[i], m1[i]);
#pragma unroll
        for (int i=0;i<55;i++) atomicAdd(&g_M2[i], m2[i]);
    }
}

// ---------------- K2: fold BN1 into w1 (exact analytic moments) ----------
__global__ void k_fold(const float* __restrict__ w1, const float* __restrict__ b1,
                       const float* __restrict__ g1, const float* __restrict__ be1){
    int d = threadIdx.x;   // 128 threads
    const double invNK = 1.0 / (double)NK;
    double wv[10];
#pragma unroll
    for (int c=0;c<10;c++) wv[c] = (double)w1[c*128 + d];
    double m = 0.0;
#pragma unroll
    for (int c=0;c<10;c++) m += ((double)g_M1[c]*invNK) * wv[c];
    double q = 0.0;
    int t = 0;
#pragma unroll
    for (int a=0;a<10;a++){
#pragma unroll
        for (int b=a;b<10;b++){
            double s2 = (double)g_M2[t++] * invNK;
            double term = s2 * wv[a] * wv[b];
            q += (a==b) ? term : 2.0*term;
        }
    }
    double var = q - m*m;                    // b1 cancels exactly
    double a1  = (double)g1[d] / sqrt(var + 1e-5);
    g_c1[d] = (float)((double)be1[d] - m*a1);
#pragma unroll
    for (int c=0;c<10;c++) g_w1p[c*128 + d] = (float)(wv[c]*a1);
    (void)b1;
}

// ---------------- K3: fused main kernel ----------------------------------
// smem layout (floats)
#define SM_W1P 0
#define SM_C1  1280
#define SM_B2  1408
#define SM_BO  1472
#define SM_W2  1536
#define SM_WS  9728
#define SM_WO  26112
#define SM_BASE 34304
#define SUBSZ 4672
// per sub-block: h[0..2047] px[2048..4095] cc[4096..4287] fx[4288..4415]
//                ob[4416..4543] s2[4544..4607] ss2[4608..4671]
#define SMEM_FLOATS (SM_BASE + 4*SUBSZ)   // 52992 floats = 211968 B

__global__ void __launch_bounds__(512,1) k_main(
    const float* __restrict__ p, const float* __restrict__ x,
    const float* __restrict__ w2, const float* __restrict__ b2,
    const float* __restrict__ ws, const float* __restrict__ wo,
    const float* __restrict__ bo, float* __restrict__ out)
{
    extern __shared__ float sm[];
    int tid = threadIdx.x;
    int s = tid >> 7;        // sub-block 0..3 (one point each)
    int u = tid & 127;
    float* hS  = sm + SM_BASE + s*SUBSZ;
    float* pxS = hS + 2048;
    float* ccS = hS + 4096;
    float* fxS = hS + 4288;
    float* obS = hS + 4416;
    float* s2S = hS + 4544;
    float* ss2S= hS + 4608;

    for (int i = tid; i < 1280;  i += 512) sm[SM_W1P+i] = g_w1p[i];
    for (int i = tid; i < 128;   i += 512) sm[SM_C1+i]  = g_c1[i];
    if (tid < 64){ sm[SM_B2+tid] = b2[tid]; sm[SM_BO+tid] = bo[tid]; }
    for (int i = tid; i < 8192;  i += 512) sm[SM_W2+i] = w2[i];
    for (int i = tid; i < 16384; i += 512) sm[SM_WS+i] = ws[i];
    for (int i = tid; i < 8192;  i += 512) sm[SM_WO+i] = wo[i];
    if (u < 64){ s2S[u]=0.f; ss2S[u]=0.f; }
    __syncthreads();

    const float* w2s = sm + SM_W2;
    const float* wss = sm + SM_WS;
    const float* wos = sm + SM_WO;

    for (int g = blockIdx.x; g < Nn/4; g += gridDim.x){
        int n = g*4 + s;

        // stage x into px[:,64:128]
        const float4* xv = (const float4*)(x + (size_t)n*1024);
#pragma unroll
        for (int f = 0; f < 2; f++){
            int fi = u + f*128;
            int k = fi >> 4, j4 = fi & 15;
            *(float4*)&pxS[k*128 + 64 + 4*j4] = xv[fi];
        }
        if (u < 48) obS[u] = p[n*48 + u];
        __syncthreads();
        if (u < 16){
            int k = u;
            float cx=obS[0], cy=obS[1], cz=obS[2];
            float qx=obS[3*k], qy=obS[3*k+1], qz=obS[3*k+2];
            float dx=cx-qx, dy=cy-qy, dz=cz-qz;
            float* c = ccS + 12*k;
            c[0]=cx;c[1]=cy;c[2]=cz;c[3]=qx;c[4]=qy;c[5]=qz;
            c[6]=dx;c[7]=dy;c[8]=dz;
            c[9]=sqrtf(dx*dx+dy*dy+dz*dz);
        }
        __syncthreads();

        // h = relu(concat @ w1' + c1)   (BN1 pre-folded)
        {
            float w[10];
#pragma unroll
            for (int c=0;c<10;c++) w[c] = sm[SM_W1P + c*128 + u];
            float cl = sm[SM_C1 + u];
#pragma unroll
            for (int k=0;k<16;k++){
                const float* cr = ccS + 12*k;
                float acc = cl;
#pragma unroll
                for (int c=0;c<10;c++) acc = fmaf(cr[c], w[c], acc);
                hS[k*128 + u] = fmaxf(acc, 0.f);
            }
        }
        __syncthreads();

        // p_c = h @ w2 + b2  -> px[:,0:64]   (f32x2 packed over d-pairs)
        {
            int e = u & 63, kh = u >> 6;
            ull acc[8];
#pragma unroll
            for (int i=0;i<8;i++) acc[i]=0ull;
            const float* hrow = hS + kh*8*128;
            for (int dp=0; dp<64; dp++){
                ull w = pk2(w2s[(2*dp)*64 + e], w2s[(2*dp+1)*64 + e]);
#pragma unroll
                for (int kk=0;kk<8;kk++){
                    ull hp = *(const ull*)(hrow + kk*128 + 2*dp);
                    ffma2(acc[kk], hp, w);
                }
            }
            float bb = sm[SM_B2 + e];
#pragma unroll
            for (int kk=0;kk<8;kk++){
                float2 a = upk2(acc[kk]);
                pxS[(kh*8+kk)*128 + e] = a.x + a.y + bb;
            }
        }
        __syncthreads();

        // logits = px @ ws  -> reuse hS     (f32x2 over c-pairs, 2 e-cols/thread)
        {
            int e0 = u & 63, kh = u >> 6;
            ull acc[16];
#pragma unroll
            for (int i=0;i<16;i++) acc[i]=0ull;
            const float* prow = pxS + kh*8*128;
            for (int cp=0; cp<64; cp++){
                ull w0 = pk2(wss[(2*cp)*128 + e0],      wss[(2*cp+1)*128 + e0]);
                ull w1v= pk2(wss[(2*cp)*128 + e0 + 64], wss[(2*cp+1)*128 + e0 + 64]);
#pragma unroll
                for (int kk=0;kk<8;kk++){
                    ull pp = *(const ull*)(prow + kk*128 + 2*cp);
                    ffma2(acc[kk],   pp, w0);
                    ffma2(acc[8+kk], pp, w1v);
                }
            }
#pragma unroll
            for (int kk=0;kk<8;kk++){
                float2 a = upk2(acc[kk]);
                float2 b = upk2(acc[8+kk]);
                hS[(kh*8+kk)*128 + e0]      = a.x + a.y;
                hS[(kh*8+kk)*128 + e0 + 64] = b.x + b.y;
            }
        }
        __syncthreads();

        // softmax over k (thread-local per channel) + weighted pool
        {
            float l[16];
#pragma unroll
            for (int k=0;k<16;k++) l[k] = hS[k*128 + u];
            float m = l[0];
#pragma unroll
            for (int k=1;k<16;k++) m = fmaxf(m, l[k]);
            float sumv = 0.f;
#pragma unroll
            for (int k=0;k<16;k++){ l[k] = __expf(l[k]-m); sumv += l[k]; }
            float f = 0.f;
#pragma unroll
            for (int k=0;k<16;k++) f = fmaf(l[k], pxS[k*128+u], f);
            fxS[u] = f / sumv;
        }
        __syncthreads();

        // out = feat @ wo + bo  (split-e reduction)
        {
            int j = u & 63, eh = u >> 6;
            float acc = 0.f;
#pragma unroll 8
            for (int e2=0;e2<64;e2++){
                int e = eh*64 + e2;
                acc = fmaf(fxS[e], wos[e*64 + j], acc);
            }
            obS[eh*64 + j] = acc;
        }
        __syncthreads();
        if (u < 64){
            float v = obS[u] + obS[64+u] + sm[SM_BO+u];
            out[(size_t)n*64 + u] = v;
            s2S[u] += v;
            ss2S[u] += v*v;
        }
        __syncthreads();
    }
    if (tid < 64){
        float a=0.f, b=0.f;
#pragma unroll
        for (int si=0; si<4; si++){
            a += sm[SM_BASE + si*SUBSZ + 4544 + tid];
            b += sm[SM_BASE + si*SUBSZ + 4608 + tid];
        }
        atomicAdd(&g_sum2[tid], a);
        atomicAdd(&g_sumsq2[tid], b);
    }
}

// ---------------- K4: finalize BN2 constants ------------------------------
__global__ void k_fin(const float* __restrict__ g2, const float* __restrict__ be2){
    int j = threadIdx.x; // 64
    double inv = 1.0 / (double)Nn;
    double mu  = (double)g_sum2[j] * inv;
    double var = (double)g_sumsq2[j] * inv - mu*mu;
    double a2  = (double)g2[j] / sqrt(var + 1e-5);
    g_a2[j] = (float)a2;
    g_c2[j] = (float)((double)be2[j] - mu*a2);
}

// ---------------- K5: in-place BN2 + relu ---------------------------------
__global__ void k_norm(float* __restrict__ out){
    __shared__ float a2s[64], c2s[64];
    if (threadIdx.x < 64){ a2s[threadIdx.x] = g_a2[threadIdx.x]; c2s[threadIdx.x] = g_c2[threadIdx.x]; }
    __syncthreads();
    const int nq = Nn*64/4;
    float4* o4 = (float4*)out;
    for (int f = blockIdx.x*blockDim.x + threadIdx.x; f < nq; f += gridDim.x*blockDim.x){
        float4 v = o4[f];
        int j = (f*4) & 63;
        v.x = fmaxf(fmaf(v.x, a2s[j],   c2s[j]),   0.f);
        v.y = fmaxf(fmaf(v.y, a2s[j+1], c2s[j+1]), 0.f);
        v.z = fmaxf(fmaf(v.z, a2s[j+2], c2s[j+2]), 0.f);
        v.w = fmaxf(fmaf(v.w, a2s[j+3], c2s[j+3]), 0.f);
        o4[f] = v;
    }
}

// ---------------- launch ---------------------------------------------------
extern "C" void kernel_launch(void* const* d_in, const int* in_sizes, int n_in,
                              void* d_out, int out_size){
    const float* p   = (const float*)d_in[0];
    const float* x   = (const float*)d_in[1];
    const float* w1  = (const float*)d_in[2];
    const float* b1  = (const float*)d_in[3];
    const float* g1  = (const float*)d_in[4];
    const float* be1 = (const float*)d_in[5];
    const float* w2  = (const float*)d_in[6];
    const float* b2  = (const float*)d_in[7];
    const float* ws  = (const float*)d_in[8];
    const float* wo  = (const float*)d_in[9];
    const float* bo  = (const float*)d_in[10];
    const float* g2  = (const float*)d_in[11];
    const float* be2 = (const float*)d_in[12];
    float* out = (float*)d_out;
    (void)in_sizes; (void)n_in; (void)out_size;

    cudaFuncSetAttribute(k_main, cudaFuncAttributeMaxDynamicSharedMemorySize,
                         SMEM_FLOATS*4);

    k_zero<<<1,64>>>();
    k_stats<<<256,256>>>(p);
    k_fold<<<1,128>>>(w1,b1,g1,be1);
    k_main<<<304,512,SMEM_FLOATS*4>>>(p,x,w2,b2,ws,wo,bo,out);
    k_fin<<<1,64>>>(g2,be2);
    k_norm<<<2048,256>>>(out);
}